// round 1
// baseline (speedup 1.0000x reference)
#include <cuda_runtime.h>
#include <math.h>

#define Hh 96
#define Ww 96
#define Bn 4
#define Cc 64
#define HW (Hh*Ww)
#define KK 9
#define CK 576           // Cc * KK
#define CIN2 130

// Scratch (device globals; no runtime allocation allowed)
__device__ float g_offset[Bn*18*HW];   // [B,18,H,W]
__device__ float g_mod[Bn*9*HW];       // [B,9,H,W]  (2*sigmoid already applied)
__device__ float g_fjt[Bn*HW*Cc];      // frame_j transposed to [B,HW,C]
__device__ float g_wflat[Cc*CK];       // w_reg reordered to [O][k*64+c]

// ---------------------------------------------------------------------------
// frame_j [B,C,H,W] -> [B,HW,C]
// ---------------------------------------------------------------------------
__global__ void k_transpose(const float* __restrict__ fj) {
    __shared__ float s[64][33];
    int b   = blockIdx.y;
    int hw0 = blockIdx.x * 32;
    int tid = threadIdx.x;
    int tx = tid & 31, ty = tid >> 5;          // ty in 0..7
#pragma unroll
    for (int i = 0; i < 8; i++) {
        int c = ty + i * 8;
        s[c][tx] = fj[(size_t)(b * Cc + c) * HW + hw0 + tx];
    }
    __syncthreads();
    int ci = tid & 63, j4 = tid >> 6;          // j4 in 0..3
#pragma unroll
    for (int i = 0; i < 8; i++) {
        int j = j4 + i * 4;
        g_fjt[(size_t)(b * HW + hw0 + j) * Cc + ci] = s[ci][j];
    }
}

// ---------------------------------------------------------------------------
// w_reg [O,C,3,3] -> g_wflat [O][k*64 + c]
// ---------------------------------------------------------------------------
__global__ void k_wflat(const float* __restrict__ w_reg) {
    int i = blockIdx.x * 256 + threadIdx.x;
    if (i < Cc * CK) {
        int o = i / CK, r = i % CK;
        int k = r >> 6, c = r & 63;
        g_wflat[i] = w_reg[(o * Cc + c) * KK + k];
    }
}

// ---------------------------------------------------------------------------
// Fused 3x3 conv: 130 in-ch -> 18 offset ch + 9 modulator ch (with 2*sigmoid)
// Block = 32x8 pixel tile, 256 threads, 27 register accumulators each.
// ---------------------------------------------------------------------------
__global__ void __launch_bounds__(256) k_conv(
    const float* __restrict__ fi, const float* __restrict__ fj,
    const float* __restrict__ fl,
    const float* __restrict__ w_off, const float* __restrict__ b_off,
    const float* __restrict__ w_mod, const float* __restrict__ b_mod)
{
    __shared__ float s_in[10 * 34];
    __shared__ float s_w[27 * 9];
    int b  = blockIdx.z;
    int x0 = blockIdx.x * 32, y0 = blockIdx.y * 8;
    int tid = threadIdx.x;
    int tx = tid & 31, ty = tid >> 5;

    float acc[27];
#pragma unroll
    for (int oc = 0; oc < 27; oc++) acc[oc] = 0.f;

    for (int cin = 0; cin < CIN2; cin++) {
        const float* src = (cin < 64)  ? fi + (size_t)(b * 64 + cin) * HW
                         : (cin < 128) ? fj + (size_t)(b * 64 + cin - 64) * HW
                                       : fl + (size_t)(b * 2 + cin - 128) * HW;
        __syncthreads();
        for (int i = tid; i < 340; i += 256) {
            int ly = i / 34, lx = i % 34;
            int gy = y0 + ly - 1, gx = x0 + lx - 1;
            s_in[i] = (gy >= 0 && gy < Hh && gx >= 0 && gx < Ww)
                        ? src[gy * Ww + gx] : 0.f;
        }
        if (tid < 243) {
            int oc = tid / 9, kk = tid % 9;
            s_w[tid] = (oc < 18) ? w_off[(oc * CIN2 + cin) * 9 + kk]
                                 : w_mod[((oc - 18) * CIN2 + cin) * 9 + kk];
        }
        __syncthreads();

        float v[9];
#pragma unroll
        for (int ky = 0; ky < 3; ky++)
#pragma unroll
            for (int kx = 0; kx < 3; kx++)
                v[ky * 3 + kx] = s_in[(ty + ky) * 34 + tx + kx];
#pragma unroll
        for (int oc = 0; oc < 27; oc++) {
            float a = acc[oc];
#pragma unroll
            for (int kk = 0; kk < 9; kk++) a += v[kk] * s_w[oc * 9 + kk];
            acc[oc] = a;
        }
    }

    int y = y0 + ty, x = x0 + tx;
#pragma unroll
    for (int oc = 0; oc < 18; oc++)
        g_offset[((size_t)(b * 18 + oc) * Hh + y) * Ww + x] = acc[oc] + b_off[oc];
#pragma unroll
    for (int mc = 0; mc < 9; mc++) {
        float z = acc[18 + mc] + b_mod[mc];
        g_mod[((size_t)(b * 9 + mc) * Hh + y) * Ww + x] = 2.f / (1.f + expf(-z));
    }
}

// ---------------------------------------------------------------------------
// Deformable conv main kernel.
// Block = one (b, y) row segment of 16 pixels.
// Phase 1: 144 threads compute bilinear corner indices/weights (mask folded in).
// Phase 2: gather 16pix x 9taps x 64ch samples into shared val[pix][k*64+c]
//          via coalesced float4 loads from channel-last frame_j.
// Phase 3: contract [16x576] with weight [64x576] (register tile 4 pixels).
// ---------------------------------------------------------------------------
__global__ void __launch_bounds__(256) k_deform(float* __restrict__ out) {
    __shared__ __align__(16) float s_val[16 * CK];
    __shared__ float s_cw[144][4];
    __shared__ int   s_ci[144][4];

    int b  = blockIdx.z;
    int y  = blockIdx.y;
    int x0 = blockIdx.x * 16;
    int tid = threadIdx.x;

    if (tid < 144) {
        int pix = tid / 9, tap = tid % 9;
        int x  = x0 + pix;
        int ky = tap / 3, kx = tap % 3;
        float offy = g_offset[((size_t)(b * 18 + 2 * tap)     * Hh + y) * Ww + x];
        float offx = g_offset[((size_t)(b * 18 + 2 * tap + 1) * Hh + y) * Ww + x];
        float m    = g_mod   [((size_t)(b * 9  + tap)         * Hh + y) * Ww + x];
        float py = (float)(y - 1 + ky) + offy;
        float px = (float)(x - 1 + kx) + offx;
        float fy = floorf(py), fx = floorf(px);
        int y0i = (int)fy, x0i = (int)fx;
        float wy = py - fy, wx = px - fx;
#pragma unroll
        for (int d = 0; d < 4; d++) {
            int dy = d >> 1, dx = d & 1;
            int yc = y0i + dy, xc = x0i + dx;
            bool ok = (yc >= 0) && (yc < Hh) && (xc >= 0) && (xc < Ww);
            float w = (dy ? wy : 1.f - wy) * (dx ? wx : 1.f - wx) * m;
            s_cw[tid][d] = ok ? w : 0.f;
            int ycc = min(max(yc, 0), Hh - 1);
            int xcc = min(max(xc, 0), Ww - 1);
            s_ci[tid][d] = ycc * Ww + xcc;
        }
    }
    __syncthreads();

    // Phase 2: gather
    {
        int c4 = (tid & 15) * 4;       // channel quad
        int jl = tid >> 4;             // pixel index (0..15)
        const float* fb = g_fjt + (size_t)b * HW * Cc;
#pragma unroll
        for (int it = 0; it < 9; it++) {
            int j = jl * 9 + it;
            float w0 = s_cw[j][0], w1 = s_cw[j][1];
            float w2 = s_cw[j][2], w3 = s_cw[j][3];
            float4 f0 = *(const float4*)(fb + (size_t)s_ci[j][0] * Cc + c4);
            float4 f1 = *(const float4*)(fb + (size_t)s_ci[j][1] * Cc + c4);
            float4 f2 = *(const float4*)(fb + (size_t)s_ci[j][2] * Cc + c4);
            float4 f3 = *(const float4*)(fb + (size_t)s_ci[j][3] * Cc + c4);
            float4 v;
            v.x = w0 * f0.x + w1 * f1.x + w2 * f2.x + w3 * f3.x;
            v.y = w0 * f0.y + w1 * f1.y + w2 * f2.y + w3 * f3.y;
            v.z = w0 * f0.z + w1 * f1.z + w2 * f2.z + w3 * f3.z;
            v.w = w0 * f0.w + w1 * f1.w + w2 * f2.w + w3 * f3.w;
            *(float4*)(s_val + jl * CK + it * 64 + c4) = v;
        }
    }
    __syncthreads();

    // Phase 3: contract. Thread -> (o = tid&63, pixel group pg = tid>>6).
    {
        int o  = tid & 63;
        int pg = tid >> 6;             // 0..3 -> pixels pg*4 .. pg*4+3
        const float4* wrow = (const float4*)(g_wflat + (size_t)o * CK);
        const float4* v0 = (const float4*)(s_val + (pg * 4 + 0) * CK);
        const float4* v1 = (const float4*)(s_val + (pg * 4 + 1) * CK);
        const float4* v2 = (const float4*)(s_val + (pg * 4 + 2) * CK);
        const float4* v3 = (const float4*)(s_val + (pg * 4 + 3) * CK);
        float a0 = 0.f, a1 = 0.f, a2 = 0.f, a3 = 0.f;
#pragma unroll 4
        for (int q = 0; q < CK / 4; q++) {
            float4 wv = __ldg(wrow + q);
            float4 t0 = v0[q], t1 = v1[q], t2 = v2[q], t3 = v3[q];
            a0 += wv.x * t0.x + wv.y * t0.y + wv.z * t0.z + wv.w * t0.w;
            a1 += wv.x * t1.x + wv.y * t1.y + wv.z * t1.z + wv.w * t1.w;
            a2 += wv.x * t2.x + wv.y * t2.y + wv.z * t2.z + wv.w * t2.w;
            a3 += wv.x * t3.x + wv.y * t3.y + wv.z * t3.z + wv.w * t3.w;
        }
        float4 r; r.x = a0; r.y = a1; r.z = a2; r.w = a3;
        *(float4*)(out + ((size_t)(b * 64 + o) * Hh + y) * Ww + x0 + pg * 4) = r;
    }
}

// ---------------------------------------------------------------------------
extern "C" void kernel_launch(void* const* d_in, const int* in_sizes, int n_in,
                              void* d_out, int out_size) {
    const float* frame_i = (const float*)d_in[0];
    const float* frame_j = (const float*)d_in[1];
    const float* flow_ij = (const float*)d_in[2];
    const float* w_off   = (const float*)d_in[3];
    const float* b_off   = (const float*)d_in[4];
    const float* w_mod   = (const float*)d_in[5];
    const float* b_mod   = (const float*)d_in[6];
    const float* w_reg   = (const float*)d_in[7];
    float* out = (float*)d_out;

    k_transpose<<<dim3(HW / 32, Bn), 256>>>(frame_j);
    k_wflat<<<(Cc * CK + 255) / 256, 256>>>(w_reg);
    k_conv<<<dim3(Ww / 32, Hh / 8, Bn), 256>>>(frame_i, frame_j, flow_ij,
                                               w_off, b_off, w_mod, b_mod);
    k_deform<<<dim3(Ww / 16, Hh, Bn), 256>>>(out);
}

// round 2
// speedup vs baseline: 2.0202x; 2.0202x over previous
#include <cuda_runtime.h>
#include <math.h>

#define Hh 96
#define Ww 96
#define Bn 4
#define Cc 64
#define HW (Hh*Ww)
#define KK 9
#define CK 576
#define CIN2 130
#define PBLK 32            // pixels per deform block
#define VPITCH 68          // s_v row pitch in floats (bank-conflict pad)

// Scratch (device globals; no runtime allocation allowed)
__device__ float g_offset[Bn*18*HW];   // [B,18,H,W]
__device__ float g_mod[Bn*9*HW];       // [B,9,H,W] (2*sigmoid applied)
__device__ float g_fjt[Bn*HW*Cc];      // frame_j as [B,HW,C]
__device__ float g_w2[KK*16*64*4];     // w_reg as [tap][chquad][o][e]

// ---------------------------------------------------------------------------
// frame_j [B,C,H,W] -> [B,HW,C]
// ---------------------------------------------------------------------------
__global__ void k_transpose(const float* __restrict__ fj) {
    __shared__ float s[64][33];
    int b   = blockIdx.y;
    int hw0 = blockIdx.x * 32;
    int tid = threadIdx.x;
    int tx = tid & 31, ty = tid >> 5;
#pragma unroll
    for (int i = 0; i < 8; i++) {
        int c = ty + i * 8;
        s[c][tx] = fj[(size_t)(b * Cc + c) * HW + hw0 + tx];
    }
    __syncthreads();
    int ci = tid & 63, j4 = tid >> 6;
#pragma unroll
    for (int i = 0; i < 8; i++) {
        int j = j4 + i * 4;
        g_fjt[(size_t)(b * HW + hw0 + j) * Cc + ci] = s[ci][j];
    }
}

// ---------------------------------------------------------------------------
// w_reg [O=64, C=64, 9] -> g_w2[tap][q][o][e] = w_reg[o][4q+e][tap]
// ---------------------------------------------------------------------------
__global__ void k_w2(const float* __restrict__ w_reg) {
    int i = blockIdx.x * 256 + threadIdx.x;
    if (i < KK * 4096) {
        int tap = i >> 12;
        int r   = i & 4095;
        int q   = r >> 8;
        int r2  = r & 255;
        int o   = r2 >> 2;
        int e   = r2 & 3;
        g_w2[i] = w_reg[(o * 64 + q * 4 + e) * KK + tap];
    }
}

// ---------------------------------------------------------------------------
// Fused 3x3 conv: 130 in-ch -> 18 offset + 9 modulator channels.
// 32x8 pixel tile, 256 threads, 27 accumulators, double-buffered staging.
// ---------------------------------------------------------------------------
__global__ void __launch_bounds__(256) k_conv(
    const float* __restrict__ fi, const float* __restrict__ fj,
    const float* __restrict__ fl,
    const float* __restrict__ w_off, const float* __restrict__ b_off,
    const float* __restrict__ w_mod, const float* __restrict__ b_mod)
{
    __shared__ float s_in[2][10 * 34];
    __shared__ float s_w[2][248];
    int b  = blockIdx.z;
    int x0 = blockIdx.x * 32, y0 = blockIdx.y * 8;
    int tid = threadIdx.x;
    int tx = tid & 31, ty = tid >> 5;

    float acc[27];
#pragma unroll
    for (int oc = 0; oc < 27; oc++) acc[oc] = 0.f;

    auto stage = [&](int cin, int buf) {
        const float* src = (cin < 64)  ? fi + (size_t)(b * 64 + cin) * HW
                         : (cin < 128) ? fj + (size_t)(b * 64 + cin - 64) * HW
                                       : fl + (size_t)(b * 2 + cin - 128) * HW;
        for (int i = tid; i < 340; i += 256) {
            int ly = i / 34, lx = i % 34;
            int gy = y0 + ly - 1, gx = x0 + lx - 1;
            s_in[buf][i] = (gy >= 0 && gy < Hh && gx >= 0 && gx < Ww)
                             ? src[gy * Ww + gx] : 0.f;
        }
        if (tid < 243) {
            int oc = tid / 9, kk = tid % 9;
            s_w[buf][tid] = (oc < 18) ? w_off[(oc * CIN2 + cin) * 9 + kk]
                                      : w_mod[((oc - 18) * CIN2 + cin) * 9 + kk];
        }
    };

    stage(0, 0);
    __syncthreads();
    for (int cin = 0; cin < CIN2; cin++) {
        int cur = cin & 1;
        if (cin + 1 < CIN2) stage(cin + 1, cur ^ 1);

        float v[9];
#pragma unroll
        for (int ky = 0; ky < 3; ky++)
#pragma unroll
            for (int kx = 0; kx < 3; kx++)
                v[ky * 3 + kx] = s_in[cur][(ty + ky) * 34 + tx + kx];
#pragma unroll
        for (int oc = 0; oc < 27; oc++) {
            float a = acc[oc];
#pragma unroll
            for (int kk = 0; kk < 9; kk++) a += v[kk] * s_w[cur][oc * 9 + kk];
            acc[oc] = a;
        }
        __syncthreads();
    }

    int y = y0 + ty, x = x0 + tx;
#pragma unroll
    for (int oc = 0; oc < 18; oc++)
        g_offset[((size_t)(b * 18 + oc) * Hh + y) * Ww + x] = acc[oc] + b_off[oc];
#pragma unroll
    for (int mc = 0; mc < 9; mc++) {
        float z = acc[18 + mc] + b_mod[mc];
        g_mod[((size_t)(b * 9 + mc) * Hh + y) * Ww + x] = 2.f / (1.f + expf(-z));
    }
}

// ---------------------------------------------------------------------------
// Deformable conv: block = 32 pixels x 64 outputs.
//   lane = pixel, warp = 8 consecutive output channels, 8 acc/thread.
//   Per tap: gather v[32pix][64ch] into s_v (bank-padded), stage w tap tile
//   into s_w, then contract with broadcast wv LDS + conflict-free tv LDS.
// ---------------------------------------------------------------------------
__global__ void __launch_bounds__(256, 3) k_deform(float* __restrict__ out) {
    __shared__ __align__(16) float s_v[PBLK * VPITCH];
    __shared__ __align__(16) float s_w[4096];
    __shared__ float s_cw[PBLK * 9][4];
    __shared__ int   s_ci[PBLK * 9][4];

    int b  = blockIdx.z;
    int y  = blockIdx.y;
    int x0 = blockIdx.x * PBLK;
    int tid = threadIdx.x;

    // Phase 1: bilinear corner weights/indices for 32 pix x 9 taps
    for (int i = tid; i < PBLK * 9; i += 256) {
        int pix = i / 9, tap = i % 9;
        int x  = x0 + pix;
        int ky = tap / 3, kx = tap % 3;
        float offy = g_offset[((size_t)(b * 18 + 2 * tap)     * Hh + y) * Ww + x];
        float offx = g_offset[((size_t)(b * 18 + 2 * tap + 1) * Hh + y) * Ww + x];
        float m    = g_mod   [((size_t)(b * 9  + tap)         * Hh + y) * Ww + x];
        float py = (float)(y - 1 + ky) + offy;
        float px = (float)(x - 1 + kx) + offx;
        float fy = floorf(py), fx = floorf(px);
        int y0i = (int)fy, x0i = (int)fx;
        float wy = py - fy, wx = px - fx;
#pragma unroll
        for (int d = 0; d < 4; d++) {
            int dy = d >> 1, dx = d & 1;
            int yc = y0i + dy, xc = x0i + dx;
            bool ok = (yc >= 0) && (yc < Hh) && (xc >= 0) && (xc < Ww);
            float w = (dy ? wy : 1.f - wy) * (dx ? wx : 1.f - wx) * m;
            s_cw[i][d] = ok ? w : 0.f;
            int ycc = min(max(yc, 0), Hh - 1);
            int xcc = min(max(xc, 0), Ww - 1);
            s_ci[i][d] = ycc * Ww + xcc;
        }
    }

    float acc[8];
#pragma unroll
    for (int oi = 0; oi < 8; oi++) acc[oi] = 0.f;

    int lane = tid & 31;            // pixel for contract
    int o0   = (tid >> 5) * 8;      // output group for contract
    int gp   = tid >> 3;            // pixel for gather
    int gq   = tid & 7;             // channel-quad base for gather
    const float* fb = g_fjt + (size_t)b * HW * Cc;

    __syncthreads();

    for (int tap = 0; tap < 9; tap++) {
        // stage weight tap tile [16 q][64 o][4 e] -> s_w (coalesced)
        {
            const float4* src = (const float4*)(g_w2 + tap * 4096);
            float4* dst = (float4*)s_w;
#pragma unroll
            for (int i = 0; i < 4; i++)
                dst[tid + i * 256] = src[tid + i * 256];
        }
        // gather: each thread does 2 channel-quads of its pixel
        {
            int j = gp * 9 + tap;
            float w0 = s_cw[j][0], w1 = s_cw[j][1];
            float w2 = s_cw[j][2], w3 = s_cw[j][3];
            const float* p0 = fb + (size_t)s_ci[j][0] * Cc;
            const float* p1 = fb + (size_t)s_ci[j][1] * Cc;
            const float* p2 = fb + (size_t)s_ci[j][2] * Cc;
            const float* p3 = fb + (size_t)s_ci[j][3] * Cc;
#pragma unroll
            for (int qq = 0; qq < 2; qq++) {
                int q = gq + qq * 8;
                float4 f0 = *(const float4*)(p0 + q * 4);
                float4 f1 = *(const float4*)(p1 + q * 4);
                float4 f2 = *(const float4*)(p2 + q * 4);
                float4 f3 = *(const float4*)(p3 + q * 4);
                float4 v;
                v.x = w0 * f0.x + w1 * f1.x + w2 * f2.x + w3 * f3.x;
                v.y = w0 * f0.y + w1 * f1.y + w2 * f2.y + w3 * f3.y;
                v.z = w0 * f0.z + w1 * f1.z + w2 * f2.z + w3 * f3.z;
                v.w = w0 * f0.w + w1 * f1.w + w2 * f2.w + w3 * f3.w;
                *(float4*)(s_v + gp * VPITCH + q * 4) = v;
            }
        }
        __syncthreads();

        // contract: tv conflict-free per-lane, wv warp-uniform broadcast
        {
            const float* vr = s_v + lane * VPITCH;
#pragma unroll
            for (int q = 0; q < 16; q++) {
                float4 tv = *(const float4*)(vr + q * 4);
#pragma unroll
                for (int oi = 0; oi < 8; oi++) {
                    float4 wv = *(const float4*)(s_w + (q * 64 + o0 + oi) * 4);
                    acc[oi] += tv.x * wv.x + tv.y * wv.y
                             + tv.z * wv.z + tv.w * wv.w;
                }
            }
        }
        __syncthreads();
    }

    // epilogue: coalesced 128B stores
#pragma unroll
    for (int oi = 0; oi < 8; oi++)
        out[((size_t)(b * 64 + o0 + oi) * Hh + y) * Ww + x0 + lane] = acc[oi];
}

// ---------------------------------------------------------------------------
extern "C" void kernel_launch(void* const* d_in, const int* in_sizes, int n_in,
                              void* d_out, int out_size) {
    const float* frame_i = (const float*)d_in[0];
    const float* frame_j = (const float*)d_in[1];
    const float* flow_ij = (const float*)d_in[2];
    const float* w_off   = (const float*)d_in[3];
    const float* b_off   = (const float*)d_in[4];
    const float* w_mod   = (const float*)d_in[5];
    const float* b_mod   = (const float*)d_in[6];
    const float* w_reg   = (const float*)d_in[7];
    float* out = (float*)d_out;

    k_transpose<<<dim3(HW / 32, Bn), 256>>>(frame_j);
    k_w2<<<(KK * 4096 + 255) / 256, 256>>>(w_reg);
    k_conv<<<dim3(Ww / 32, Hh / 8, Bn), 256>>>(frame_i, frame_j, flow_ij,
                                               w_off, b_off, w_mod, b_mod);
    k_deform<<<dim3(Ww / PBLK, Hh, Bn), 256>>>(out);
}